// round 1
// baseline (speedup 1.0000x reference)
#include <cuda_runtime.h>
#include <cuda_bf16.h>

#define BB 8
#define PP 196
#define ROWS (BB*PP)   // 1568
#define IT 14
#define JT 49
#define K2P 20         // padded pitch for k2 rows (16 used) -> <=2-way smem conflicts

// Scratch (allocation-free rule: __device__ globals)
__device__ __align__(16) float g_G[ROWS * 256];     // G[b,j][h*16+d], 1.6 MB
__device__ __align__(16) float g_feat[ROWS * 32];
__device__ float g_Sbias[BB * 16];

// ---------------------------------------------------------------------------
// Kernel A: decode MLP per (b,p) row + G precompute.
// 1 warp per row, 8 rows per block, grid = 196.
// ---------------------------------------------------------------------------
__global__ __launch_bounds__(256) void decode_kernel(
    const float* __restrict__ feature, const float* __restrict__ pe,
    const float* __restrict__ dW1, const float* __restrict__ db1,
    const float* __restrict__ dW2, const float* __restrict__ db2,
    const float* __restrict__ dW3, const float* __restrict__ db3,
    const float* __restrict__ kW3)
{
    __shared__ float s_kW3[16 * 512];
    __shared__ float s_x[8][124];
    __shared__ float s_h1[8][32];
    __shared__ float s_h2[8][16];
    __shared__ float s_f[8][33];

    int tid = threadIdx.x;
    // stage kW3 (32 KB) cooperatively
    for (int q = tid; q < 2048; q += 256)
        ((float4*)s_kW3)[q] = ((const float4*)kW3)[q];

    int warp = tid >> 5, lane = tid & 31;
    int row = blockIdx.x * 8 + warp;          // row = b*P + p, < 1568
    int b = row / PP;

    // build x = [feature(64) | pe(60)]
    const float* fb = feature + b * 64;
    const float* pr = pe + row * 60;
    s_x[warp][lane]      = fb[lane];
    s_x[warp][32 + lane] = fb[32 + lane];
    s_x[warp][64 + lane] = pr[lane];
    if (lane < 28) s_x[warp][96 + lane] = pr[32 + lane];
    __syncwarp();

    // h1[32] = relu(x @ dW1 + db1); lane = output neuron
    {
        float a = __ldg(db1 + lane);
        #pragma unroll 4
        for (int k = 0; k < 124; k++)
            a = fmaf(s_x[warp][k], __ldg(dW1 + k * 32 + lane), a);
        s_h1[warp][lane] = fmaxf(a, 0.f);
    }
    __syncwarp();
    // h2[16]
    if (lane < 16) {
        float a = __ldg(db2 + lane);
        #pragma unroll
        for (int k = 0; k < 32; k++)
            a = fmaf(s_h1[warp][k], __ldg(dW2 + k * 16 + lane), a);
        s_h2[warp][lane] = fmaxf(a, 0.f);
    }
    __syncwarp();
    // feat[32]
    {
        float a = __ldg(db3 + lane);
        #pragma unroll
        for (int k = 0; k < 16; k++)
            a = fmaf(s_h2[warp][k], __ldg(dW3 + k * 32 + lane), a);
        float f = fmaxf(a, 0.f);
        s_f[warp][lane] = f;
        g_feat[row * 32 + lane] = f;
    }
    __syncthreads();   // s_kW3 fully staged + s_f visible

    // G[row][h*16+d] = sum_c feat[c] * kW3[h*512 + c*16 + d]
    // lane covers hd = lane + 32*t  =>  h = (lane>>4) + 2t, d = lane&15
    float g[8];
    #pragma unroll
    for (int t = 0; t < 8; t++) g[t] = 0.f;
    int d = lane & 15;
    int hbase = lane >> 4;
    #pragma unroll 4
    for (int c = 0; c < 32; c++) {
        float f = s_f[warp][c];
        #pragma unroll
        for (int t = 0; t < 8; t++)
            g[t] = fmaf(f, s_kW3[(hbase + 2 * t) * 512 + c * 16 + d], g[t]);
    }
    float* Gr = g_G + row * 256;
    #pragma unroll
    for (int t = 0; t < 8; t++) Gr[lane + 32 * t] = g[t];
}

// ---------------------------------------------------------------------------
// Kernel C: Sbias[b,d] = sum_c (sum_j feat[b,j,c]) * kb3[c*16+d]
// ---------------------------------------------------------------------------
__global__ void sbias_kernel(const float* __restrict__ kb3)
{
    int b = blockIdx.x;
    int c = threadIdx.x;               // 32 threads
    __shared__ float fs[32];
    float s = 0.f;
    const float* f = g_feat + b * PP * 32 + c;
    for (int j = 0; j < PP; j++) s += f[j * 32];
    fs[c] = s;
    __syncwarp();
    if (c < 16) {
        float sb = 0.f;
        #pragma unroll
        for (int k = 0; k < 32; k++)
            sb = fmaf(fs[k], __ldg(kb3 + k * 16 + c), sb);
        g_Sbias[b * 16 + c] = sb;
    }
}

// ---------------------------------------------------------------------------
// Kernel B (hot): out[b,i,d] = relu( Sbias[b,d] + sum_{j,h} k2[i,j,h]*G[j,h,d] )
// One block per (b, 14-row i-tile). 224 threads: thread = (i = tid>>4, d = tid&15).
// j processed in 4 tiles of 49: phase1 computes pair MLP k2 into smem + stages G,
// phase2 accumulates.
// ---------------------------------------------------------------------------
__global__ __launch_bounds__(224) void pair_kernel(
    const float* __restrict__ coords,
    const float* __restrict__ kW1, const float* __restrict__ kb1,
    const float* __restrict__ kW2, const float* __restrict__ kb2,
    float* __restrict__ out)
{
    extern __shared__ float sm[];
    float* s_k2 = sm;                          // IT*JT*K2P = 13720 floats
    float* s_G  = sm + IT * JT * K2P;          // JT*256   = 12544 floats
    float* s_w  = s_G + JT * 256;              // 176 floats (kW1,kb1,kW2,kb2)
    float* s_ci = s_w + 176;                   // 42 floats

    int tid = threadIdx.x;
    int b = blockIdx.x / IT;
    int itile = blockIdx.x % IT;
    int i0 = itile * IT;

    if (tid < 176) {
        float v;
        if (tid < 24)       v = kW1[tid];
        else if (tid < 32)  v = kb1[tid - 24];
        else if (tid < 160) v = kW2[tid - 32];
        else                v = kb2[tid - 160];
        s_w[tid] = v;
    }
    if (tid < IT * 3) s_ci[tid] = coords[(b * PP + i0) * 3 + tid];

    int i = tid >> 4;
    int d = tid & 15;
    float acc0 = g_Sbias[b * 16 + d];
    float acc1 = 0.f, acc2s = 0.f, acc3 = 0.f;

    const float4* w2 = (const float4*)(s_w + 32);    // kW2 as float4 rows
    const float4* b2 = (const float4*)(s_w + 160);   // kb2

    for (int t = 0; t < 4; t++) {
        int j0 = t * JT;
        __syncthreads();   // prior phase-2 done (t=0: initial smem loads done)

        // stage G tile (coalesced float4)
        {
            const float4* src = (const float4*)(g_G + (b * PP + j0) * 256);
            float4* dst = (float4*)s_G;
            for (int q = tid; q < JT * 64; q += 224) dst[q] = src[q];
        }

        // pair MLP: 686 pairs over 224 threads
        for (int q = tid; q < IT * JT; q += 224) {
            int ii = q / JT;
            int jj = q - ii * JT;
            const float* cj = coords + (b * PP + j0 + jj) * 3;
            float r0 = cj[0] - s_ci[ii * 3 + 0];
            float r1 = cj[1] - s_ci[ii * 3 + 1];
            float r2 = cj[2] - s_ci[ii * 3 + 2];

            float a1[8];
            #pragma unroll
            for (int n = 0; n < 8; n++) {
                float a = s_w[24 + n];
                a = fmaf(r0, s_w[n], a);
                a = fmaf(r1, s_w[8 + n], a);
                a = fmaf(r2, s_w[16 + n], a);
                a1[n] = fmaxf(a, 0.f);
            }
            float a2[16];
            {
                float4 v0 = b2[0], v1 = b2[1], v2 = b2[2], v3 = b2[3];
                a2[0]=v0.x; a2[1]=v0.y; a2[2]=v0.z; a2[3]=v0.w;
                a2[4]=v1.x; a2[5]=v1.y; a2[6]=v1.z; a2[7]=v1.w;
                a2[8]=v2.x; a2[9]=v2.y; a2[10]=v2.z; a2[11]=v2.w;
                a2[12]=v3.x; a2[13]=v3.y; a2[14]=v3.z; a2[15]=v3.w;
            }
            #pragma unroll
            for (int k = 0; k < 8; k++) {
                float a = a1[k];
                #pragma unroll
                for (int n4 = 0; n4 < 4; n4++) {
                    float4 w = w2[k * 4 + n4];
                    a2[n4*4+0] = fmaf(a, w.x, a2[n4*4+0]);
                    a2[n4*4+1] = fmaf(a, w.y, a2[n4*4+1]);
                    a2[n4*4+2] = fmaf(a, w.z, a2[n4*4+2]);
                    a2[n4*4+3] = fmaf(a, w.w, a2[n4*4+3]);
                }
            }
            float4* dst = (float4*)(s_k2 + q * K2P);
            #pragma unroll
            for (int n4 = 0; n4 < 4; n4++) {
                float4 v;
                v.x = fmaxf(a2[n4*4+0], 0.f);
                v.y = fmaxf(a2[n4*4+1], 0.f);
                v.z = fmaxf(a2[n4*4+2], 0.f);
                v.w = fmaxf(a2[n4*4+3], 0.f);
                dst[n4] = v;
            }
        }
        __syncthreads();

        // contraction: acc += sum_{jj,h} k2[i,jj,h] * G[jj,h*16+d]
        const float* Gd = s_G + d;
        const float* k2i = s_k2 + i * JT * K2P;
        #pragma unroll 1
        for (int jj = 0; jj < JT; jj++) {
            const float4* k4 = (const float4*)(k2i + jj * K2P);
            const float* Gj = Gd + jj * 256;
            float4 ka = k4[0];
            float4 kb = k4[1];
            float4 kc = k4[2];
            float4 kd = k4[3];
            acc0 = fmaf(ka.x, Gj[0],   acc0);
            acc1 = fmaf(ka.y, Gj[16],  acc1);
            acc2s= fmaf(ka.z, Gj[32],  acc2s);
            acc3 = fmaf(ka.w, Gj[48],  acc3);
            acc0 = fmaf(kb.x, Gj[64],  acc0);
            acc1 = fmaf(kb.y, Gj[80],  acc1);
            acc2s= fmaf(kb.z, Gj[96],  acc2s);
            acc3 = fmaf(kb.w, Gj[112], acc3);
            acc0 = fmaf(kc.x, Gj[128], acc0);
            acc1 = fmaf(kc.y, Gj[144], acc1);
            acc2s= fmaf(kc.z, Gj[160], acc2s);
            acc3 = fmaf(kc.w, Gj[176], acc3);
            acc0 = fmaf(kd.x, Gj[192], acc0);
            acc1 = fmaf(kd.y, Gj[208], acc1);
            acc2s= fmaf(kd.z, Gj[224], acc2s);
            acc3 = fmaf(kd.w, Gj[240], acc3);
        }
    }
    float r = (acc0 + acc1) + (acc2s + acc3);
    out[(b * PP + i0 + i) * 16 + d] = fmaxf(r, 0.f);
}

// ---------------------------------------------------------------------------
extern "C" void kernel_launch(void* const* d_in, const int* in_sizes, int n_in,
                              void* d_out, int out_size)
{
    const float* feature = (const float*)d_in[0];
    const float* pe      = (const float*)d_in[1];
    const float* coords  = (const float*)d_in[2];
    const float* dW1 = (const float*)d_in[3];
    const float* db1 = (const float*)d_in[4];
    const float* dW2 = (const float*)d_in[5];
    const float* db2 = (const float*)d_in[6];
    const float* dW3 = (const float*)d_in[7];
    const float* db3 = (const float*)d_in[8];
    const float* kW1 = (const float*)d_in[9];
    const float* kb1 = (const float*)d_in[10];
    const float* kW2 = (const float*)d_in[11];
    const float* kb2 = (const float*)d_in[12];
    const float* kW3 = (const float*)d_in[13];
    const float* kb3 = (const float*)d_in[14];
    float* out = (float*)d_out;

    const int smemB = (IT * JT * K2P + JT * 256 + 176 + 64) * (int)sizeof(float);
    cudaFuncSetAttribute(pair_kernel, cudaFuncAttributeMaxDynamicSharedMemorySize, smemB);

    decode_kernel<<<196, 256>>>(feature, pe, dW1, db1, dW2, db2, dW3, db3, kW3);
    sbias_kernel<<<BB, 32>>>(kb3);
    pair_kernel<<<BB * IT, 224, smemB>>>(coords, kW1, kb1, kW2, kb2, out);
}

// round 2
// speedup vs baseline: 1.2294x; 1.2294x over previous
#include <cuda_runtime.h>
#include <cuda_bf16.h>

#define BB 8
#define PP 196
#define ROWS (BB*PP)   // 1568
#define IT 14
#define JT 49
#define K2P 20         // padded pitch for k2 rows (16 used)

// Scratch (allocation-free rule: __device__ globals)
__device__ __align__(16) float g_G[ROWS * 256];     // G[b,j][h*16+d]
__device__ __align__(16) float g_feat[ROWS * 32];
__device__ float g_Sbias[BB * 16];

// ---------------------------------------------------------------------------
// Kernel A: decode MLP -> feat. 1 warp per row, 8 rows/block, grid=196.
// All weights smem-resident; split accumulators for ILP.
// ---------------------------------------------------------------------------
__global__ __launch_bounds__(256) void feat_kernel(
    const float* __restrict__ feature, const float* __restrict__ pe,
    const float* __restrict__ dW1, const float* __restrict__ db1,
    const float* __restrict__ dW2, const float* __restrict__ db2,
    const float* __restrict__ dW3, const float* __restrict__ db3)
{
    __shared__ float s_W1[124 * 32];
    __shared__ float s_W2[32 * 16];
    __shared__ float s_W3[16 * 32];
    __shared__ float s_b1[32], s_b2[16], s_b3[32];
    __shared__ float s_x[8][124];
    __shared__ float s_h1[8][32];
    __shared__ float s_h2[8][16];

    int tid = threadIdx.x;
    for (int q = tid; q < 3968; q += 256) s_W1[q] = dW1[q];
    for (int q = tid; q < 512;  q += 256) s_W2[q] = dW2[q];
    for (int q = tid; q < 512;  q += 256) s_W3[q] = dW3[q];
    if (tid < 32) s_b1[tid] = db1[tid];
    if (tid < 16) s_b2[tid] = db2[tid];
    if (tid < 32) s_b3[tid] = db3[tid];

    int warp = tid >> 5, lane = tid & 31;
    int row = blockIdx.x * 8 + warp;
    int b = row / PP;

    const float* fb = feature + b * 64;
    const float* pr = pe + row * 60;
    s_x[warp][lane]      = fb[lane];
    s_x[warp][32 + lane] = fb[32 + lane];
    s_x[warp][64 + lane] = pr[lane];
    if (lane < 28) s_x[warp][96 + lane] = pr[32 + lane];
    __syncthreads();   // weights + x staged

    // h1[32]
    {
        float a0 = s_b1[lane], a1 = 0.f, a2 = 0.f, a3 = 0.f;
        const float* xr = s_x[warp];
        #pragma unroll
        for (int k = 0; k < 124; k += 4) {
            a0 = fmaf(xr[k],     s_W1[(k)     * 32 + lane], a0);
            a1 = fmaf(xr[k + 1], s_W1[(k + 1) * 32 + lane], a1);
            a2 = fmaf(xr[k + 2], s_W1[(k + 2) * 32 + lane], a2);
            a3 = fmaf(xr[k + 3], s_W1[(k + 3) * 32 + lane], a3);
        }
        s_h1[warp][lane] = fmaxf((a0 + a1) + (a2 + a3), 0.f);
    }
    __syncwarp();
    // h2[16]
    if (lane < 16) {
        float a0 = s_b2[lane], a1 = 0.f;
        #pragma unroll
        for (int k = 0; k < 32; k += 2) {
            a0 = fmaf(s_h1[warp][k],     s_W2[(k)     * 16 + lane], a0);
            a1 = fmaf(s_h1[warp][k + 1], s_W2[(k + 1) * 16 + lane], a1);
        }
        s_h2[warp][lane] = fmaxf(a0 + a1, 0.f);
    }
    __syncwarp();
    // feat[32]
    {
        float a0 = s_b3[lane], a1 = 0.f;
        #pragma unroll
        for (int k = 0; k < 16; k += 2) {
            a0 = fmaf(s_h2[warp][k],     s_W3[(k)     * 32 + lane], a0);
            a1 = fmaf(s_h2[warp][k + 1], s_W3[(k + 1) * 32 + lane], a1);
        }
        g_feat[row * 32 + lane] = fmaxf(a0 + a1, 0.f);
    }
}

// ---------------------------------------------------------------------------
// Kernel B: G[row][h*16+d] = sum_c feat[row][c] * kW3[h*512 + c*16 + d]
// 98 blocks x 256 threads; block = 16 rows; thread = one output column hd.
// kW3 reordered in smem to s_w[c][hd] (pitch 264) -> conflict-free loads.
// ---------------------------------------------------------------------------
__global__ __launch_bounds__(256) void G_kernel(const float* __restrict__ kW3)
{
    __shared__ float s_w[32 * 264];
    __shared__ float s_feat[16][33];

    int tid = threadIdx.x;
    for (int q = tid; q < 8192; q += 256) {
        int h = q >> 9;
        int rem = q & 511;
        int c = rem >> 4;
        int d = rem & 15;
        s_w[c * 264 + h * 16 + d] = kW3[q];
    }
    int r0 = blockIdx.x * 16;
    for (int q = tid; q < 16 * 32; q += 256)
        s_feat[q >> 5][q & 31] = g_feat[r0 * 32 + q];
    __syncthreads();

    int hd = tid;   // 0..255
    #pragma unroll 2
    for (int r = 0; r < 16; r++) {
        const float* fr = s_feat[r];
        float a0 = 0.f, a1 = 0.f, a2 = 0.f, a3 = 0.f;
        #pragma unroll
        for (int c = 0; c < 32; c += 4) {
            a0 = fmaf(fr[c],     s_w[(c)     * 264 + hd], a0);
            a1 = fmaf(fr[c + 1], s_w[(c + 1) * 264 + hd], a1);
            a2 = fmaf(fr[c + 2], s_w[(c + 2) * 264 + hd], a2);
            a3 = fmaf(fr[c + 3], s_w[(c + 3) * 264 + hd], a3);
        }
        g_G[(r0 + r) * 256 + hd] = (a0 + a1) + (a2 + a3);
    }
}

// ---------------------------------------------------------------------------
// Kernel C: Sbias[b,d] = sum_c (sum_j feat[b,j,c]) * kb3[c*16+d]
// ---------------------------------------------------------------------------
__global__ void sbias_kernel(const float* __restrict__ kb3)
{
    int b = blockIdx.x;
    int c = threadIdx.x;               // 32 threads
    __shared__ float fs[32];
    float s = 0.f;
    const float* f = g_feat + b * PP * 32 + c;
    for (int j = 0; j < PP; j++) s += f[j * 32];
    fs[c] = s;
    __syncwarp();
    if (c < 16) {
        float sb = 0.f;
        #pragma unroll
        for (int k = 0; k < 32; k++)
            sb = fmaf(fs[k], __ldg(kb3 + k * 16 + c), sb);
        g_Sbias[b * 16 + c] = sb;
    }
}

// ---------------------------------------------------------------------------
// Kernel D (hot): out[b,i,d] = relu( Sbias[b,d] + sum_{j,h} k2[i,j,h]*G[j,h,d] )
// Block = (b, 14-row i-tile); 224 threads / 7 warps.
// Contraction: warp w owns jj in {w*7..w*7+6}; lane = (g = lane>>4, d = lane&15);
// thread holds G[jj,:,d] in 16 regs, reused across 7 i-accumulators (i = g*7+t).
// Cross-warp partial sums reduced once at the end.
// ---------------------------------------------------------------------------
__global__ __launch_bounds__(224) void pair_kernel(
    const float* __restrict__ coords,
    const float* __restrict__ kW1, const float* __restrict__ kb1,
    const float* __restrict__ kW2, const float* __restrict__ kb2,
    float* __restrict__ out)
{
    extern __shared__ float sm[];
    float* s_k2  = sm;                           // IT*JT*K2P = 13720
    float* s_G   = s_k2 + IT * JT * K2P;         // JT*256    = 12544
    float* s_w   = s_G + JT * 256;               // 176
    float* s_ci  = s_w + 176;                    // 48
    float* s_red = s_ci + 48;                    // 7*224 = 1568

    int tid = threadIdx.x;
    int b = blockIdx.x / IT;
    int itile = blockIdx.x % IT;
    int i0 = itile * IT;

    if (tid < 176) {
        float v;
        if (tid < 24)       v = kW1[tid];
        else if (tid < 32)  v = kb1[tid - 24];
        else if (tid < 160) v = kW2[tid - 32];
        else                v = kb2[tid - 160];
        s_w[tid] = v;
    }
    if (tid < IT * 3) s_ci[tid] = coords[(b * PP + i0) * 3 + tid];

    int w = tid >> 5, lane = tid & 31;
    int g = lane >> 4, d = lane & 15;

    float acc[7];
    #pragma unroll
    for (int t = 0; t < 7; t++) acc[t] = 0.f;

    const float4* w2 = (const float4*)(s_w + 32);
    const float4* b2 = (const float4*)(s_w + 160);

    for (int tt = 0; tt < 4; tt++) {
        int j0 = tt * JT;
        __syncthreads();   // prior contraction done (t=0: initial smem loads done)

        // stage G tile (coalesced float4)
        {
            const float4* src = (const float4*)(g_G + (b * PP + j0) * 256);
            float4* dst = (float4*)s_G;
            for (int q = tid; q < JT * 64; q += 224) dst[q] = src[q];
        }

        // pair MLP: 686 pairs over 224 threads
        for (int q = tid; q < IT * JT; q += 224) {
            int ii = q / JT;
            int jj = q - ii * JT;
            const float* cj = coords + (b * PP + j0 + jj) * 3;
            float r0 = cj[0] - s_ci[ii * 3 + 0];
            float r1 = cj[1] - s_ci[ii * 3 + 1];
            float r2 = cj[2] - s_ci[ii * 3 + 2];

            float a1[8];
            #pragma unroll
            for (int n = 0; n < 8; n++) {
                float a = s_w[24 + n];
                a = fmaf(r0, s_w[n], a);
                a = fmaf(r1, s_w[8 + n], a);
                a = fmaf(r2, s_w[16 + n], a);
                a1[n] = fmaxf(a, 0.f);
            }
            float a2[16];
            {
                float4 v0 = b2[0], v1 = b2[1], v2 = b2[2], v3 = b2[3];
                a2[0]=v0.x; a2[1]=v0.y; a2[2]=v0.z; a2[3]=v0.w;
                a2[4]=v1.x; a2[5]=v1.y; a2[6]=v1.z; a2[7]=v1.w;
                a2[8]=v2.x; a2[9]=v2.y; a2[10]=v2.z; a2[11]=v2.w;
                a2[12]=v3.x; a2[13]=v3.y; a2[14]=v3.z; a2[15]=v3.w;
            }
            #pragma unroll
            for (int k = 0; k < 8; k++) {
                float a = a1[k];
                #pragma unroll
                for (int n4 = 0; n4 < 4; n4++) {
                    float4 wv = w2[k * 4 + n4];
                    a2[n4*4+0] = fmaf(a, wv.x, a2[n4*4+0]);
                    a2[n4*4+1] = fmaf(a, wv.y, a2[n4*4+1]);
                    a2[n4*4+2] = fmaf(a, wv.z, a2[n4*4+2]);
                    a2[n4*4+3] = fmaf(a, wv.w, a2[n4*4+3]);
                }
            }
            float4* dst = (float4*)(s_k2 + q * K2P);
            #pragma unroll
            for (int n4 = 0; n4 < 4; n4++) {
                float4 v;
                v.x = fmaxf(a2[n4*4+0], 0.f);
                v.y = fmaxf(a2[n4*4+1], 0.f);
                v.z = fmaxf(a2[n4*4+2], 0.f);
                v.w = fmaxf(a2[n4*4+3], 0.f);
                dst[n4] = v;
            }
        }
        __syncthreads();

        // contraction: warp w handles jj = w*7 .. w*7+6
        #pragma unroll 1
        for (int m = 0; m < 7; m++) {
            int jj = w * 7 + m;
            const float* Gj = s_G + jj * 256 + d;
            float Gv[16];
            #pragma unroll
            for (int h = 0; h < 16; h++) Gv[h] = Gj[h * 16];
            #pragma unroll
            for (int t = 0; t < 7; t++) {
                int i = g * 7 + t;
                const float4* k4 = (const float4*)(s_k2 + (i * JT + jj) * K2P);
                float4 ka = k4[0], kb = k4[1], kc = k4[2], kd = k4[3];
                float a = acc[t];
                a = fmaf(ka.x, Gv[0],  a);
                a = fmaf(ka.y, Gv[1],  a);
                a = fmaf(ka.z, Gv[2],  a);
                a = fmaf(ka.w, Gv[3],  a);
                a = fmaf(kb.x, Gv[4],  a);
                a = fmaf(kb.y, Gv[5],  a);
                a = fmaf(kb.z, Gv[6],  a);
                a = fmaf(kb.w, Gv[7],  a);
                a = fmaf(kc.x, Gv[8],  a);
                a = fmaf(kc.y, Gv[9],  a);
                a = fmaf(kc.z, Gv[10], a);
                a = fmaf(kc.w, Gv[11], a);
                a = fmaf(kd.x, Gv[12], a);
                a = fmaf(kd.y, Gv[13], a);
                a = fmaf(kd.z, Gv[14], a);
                a = fmaf(kd.w, Gv[15], a);
                acc[t] = a;
            }
        }
    }

    // cross-warp reduction
    __syncthreads();
    #pragma unroll
    for (int t = 0; t < 7; t++)
        s_red[w * 224 + (g * 7 + t) * 16 + d] = acc[t];
    __syncthreads();
    {
        int i = tid >> 4;
        int dd = tid & 15;
        float s = g_Sbias[b * 16 + dd];
        #pragma unroll
        for (int ww = 0; ww < 7; ww++) s += s_red[ww * 224 + tid];
        out[(b * PP + i0 + i) * 16 + dd] = fmaxf(s, 0.f);
    }
}

// ---------------------------------------------------------------------------
extern "C" void kernel_launch(void* const* d_in, const int* in_sizes, int n_in,
                              void* d_out, int out_size)
{
    const float* feature = (const float*)d_in[0];
    const float* pe      = (const float*)d_in[1];
    const float* coords  = (const float*)d_in[2];
    const float* dW1 = (const float*)d_in[3];
    const float* db1 = (const float*)d_in[4];
    const float* dW2 = (const float*)d_in[5];
    const float* db2 = (const float*)d_in[6];
    const float* dW3 = (const float*)d_in[7];
    const float* db3 = (const float*)d_in[8];
    const float* kW1 = (const float*)d_in[9];
    const float* kb1 = (const float*)d_in[10];
    const float* kW2 = (const float*)d_in[11];
    const float* kb2 = (const float*)d_in[12];
    const float* kW3 = (const float*)d_in[13];
    const float* kb3 = (const float*)d_in[14];
    float* out = (float*)d_out;

    const int smemB = (IT * JT * K2P + JT * 256 + 176 + 48 + 7 * 224) * (int)sizeof(float);
    static bool attr_set = false;
    if (!attr_set) {
        cudaFuncSetAttribute(pair_kernel, cudaFuncAttributeMaxDynamicSharedMemorySize, smemB);
        attr_set = true;
    }

    feat_kernel<<<196, 256>>>(feature, pe, dW1, db1, dW2, db2, dW3, db3);
    G_kernel<<<98, 256>>>(kW3);
    sbias_kernel<<<BB, 32>>>(kb3);
    pair_kernel<<<BB * IT, 224, smemB>>>(coords, kW1, kb1, kW2, kb2, out);
}

// round 5
// speedup vs baseline: 1.4365x; 1.1685x over previous
#include <cuda_runtime.h>
#include <cuda_bf16.h>

#define BB 8
#define PP 196
#define ROWS (BB*PP)   // 1568
#define IT 7
#define NIT 28         // i-tiles per batch
#define JT 49
#define K2P 20         // padded pitch for k2 rows (16 used)

// Scratch (allocation-free rule: __device__ globals)
__device__ __align__(16) float g_G[ROWS * 256];     // G[b,j][h*16+d]
__device__ __align__(16) float g_feat[ROWS * 32];
__device__ float g_Sbias[BB * 16];

// feat_G dynamic-smem layout (floats):
#define FG_W1   0                    // 124*32 = 3968
#define FG_W2   (FG_W1 + 3968)       // 512
#define FG_W3   (FG_W2 + 512)        // 512
#define FG_B1   (FG_W3 + 512)        // 32
#define FG_B2   (FG_B1 + 32)         // 16
#define FG_B3   (FG_B2 + 16)         // 32
#define FG_KW   (FG_B3 + 32)         // 32*264 = 8448
#define FG_X    (FG_KW + 8448)       // 8*124 = 992
#define FG_H1   (FG_X + 992)         // 8*32 = 256
#define FG_H2   (FG_H1 + 256)        // 8*16 = 128
#define FG_F    (FG_H2 + 128)        // 8*33 = 264
#define FG_TOT  (FG_F + 264)         // 15160 floats = 60640 B

// ---------------------------------------------------------------------------
// Kernel A (fused): decode MLP -> feat, then G = feat @ reordered kW3.
// 196 blocks x 256 threads; warp-per-row decode (8 rows), thread-per-column G.
// ---------------------------------------------------------------------------
__global__ __launch_bounds__(256) void feat_G_kernel(
    const float* __restrict__ feature, const float* __restrict__ pe,
    const float* __restrict__ dW1, const float* __restrict__ db1,
    const float* __restrict__ dW2, const float* __restrict__ db2,
    const float* __restrict__ dW3, const float* __restrict__ db3,
    const float* __restrict__ kW3)
{
    extern __shared__ float sm[];
    float* s_W1 = sm + FG_W1;
    float* s_W2 = sm + FG_W2;
    float* s_W3 = sm + FG_W3;
    float* s_b1 = sm + FG_B1;
    float* s_b2 = sm + FG_B2;
    float* s_b3 = sm + FG_B3;
    float* s_kw = sm + FG_KW;
    float* s_x  = sm + FG_X;     // [8][124]
    float* s_h1 = sm + FG_H1;    // [8][32]
    float* s_h2 = sm + FG_H2;    // [8][16]
    float* s_f  = sm + FG_F;     // [8][33]

    int tid = threadIdx.x;
    // stage weights
    for (int q = tid; q < 992; q += 256)
        ((float4*)s_W1)[q] = ((const float4*)dW1)[q];
    for (int q = tid; q < 512; q += 256) s_W2[q] = dW2[q];
    for (int q = tid; q < 512; q += 256) s_W3[q] = dW3[q];
    if (tid < 32) s_b1[tid] = db1[tid];
    if (tid < 16) s_b2[tid] = db2[tid];
    if (tid < 32) s_b3[tid] = db3[tid];
    for (int q = tid; q < 8192; q += 256) {
        int h = q >> 9;
        int rem = q & 511;
        int c = rem >> 4;
        int d = rem & 15;
        s_kw[c * 264 + h * 16 + d] = kW3[q];
    }

    int warp = tid >> 5, lane = tid & 31;
    int row = blockIdx.x * 8 + warp;
    int b = row / PP;

    const float* fb = feature + b * 64;
    const float* pr = pe + row * 60;
    float* xr = s_x + warp * 124;
    xr[lane]      = fb[lane];
    xr[32 + lane] = fb[32 + lane];
    xr[64 + lane] = pr[lane];
    if (lane < 28) xr[96 + lane] = pr[32 + lane];
    __syncthreads();

    // h1[32]
    {
        float a0 = s_b1[lane], a1 = 0.f, a2 = 0.f, a3 = 0.f;
        #pragma unroll
        for (int k = 0; k < 124; k += 4) {
            a0 = fmaf(xr[k],     s_W1[(k)     * 32 + lane], a0);
            a1 = fmaf(xr[k + 1], s_W1[(k + 1) * 32 + lane], a1);
            a2 = fmaf(xr[k + 2], s_W1[(k + 2) * 32 + lane], a2);
            a3 = fmaf(xr[k + 3], s_W1[(k + 3) * 32 + lane], a3);
        }
        s_h1[warp * 32 + lane] = fmaxf((a0 + a1) + (a2 + a3), 0.f);
    }
    __syncwarp();
    // h2[16]
    if (lane < 16) {
        float a0 = s_b2[lane], a1 = 0.f;
        #pragma unroll
        for (int k = 0; k < 32; k += 2) {
            a0 = fmaf(s_h1[warp * 32 + k],     s_W2[(k)     * 16 + lane], a0);
            a1 = fmaf(s_h1[warp * 32 + k + 1], s_W2[(k + 1) * 16 + lane], a1);
        }
        s_h2[warp * 16 + lane] = fmaxf(a0 + a1, 0.f);
    }
    __syncwarp();
    // feat[32]
    {
        float a0 = s_b3[lane], a1 = 0.f;
        #pragma unroll
        for (int k = 0; k < 16; k += 2) {
            a0 = fmaf(s_h2[warp * 16 + k],     s_W3[(k)     * 32 + lane], a0);
            a1 = fmaf(s_h2[warp * 16 + k + 1], s_W3[(k + 1) * 32 + lane], a1);
        }
        float f = fmaxf(a0 + a1, 0.f);
        s_f[warp * 33 + lane] = f;
        g_feat[row * 32 + lane] = f;
    }
    __syncthreads();

    // G[r0+r][hd] = sum_c s_f[r][c] * s_kw[c][hd], hd = tid
    int r0 = blockIdx.x * 8;
    int hd = tid;
    #pragma unroll 2
    for (int r = 0; r < 8; r++) {
        const float* fr = s_f + r * 33;
        float a0 = 0.f, a1 = 0.f, a2 = 0.f, a3 = 0.f;
        #pragma unroll
        for (int c = 0; c < 32; c += 4) {
            a0 = fmaf(fr[c],     s_kw[(c)     * 264 + hd], a0);
            a1 = fmaf(fr[c + 1], s_kw[(c + 1) * 264 + hd], a1);
            a2 = fmaf(fr[c + 2], s_kw[(c + 2) * 264 + hd], a2);
            a3 = fmaf(fr[c + 3], s_kw[(c + 3) * 264 + hd], a3);
        }
        g_G[(r0 + r) * 256 + hd] = (a0 + a1) + (a2 + a3);
    }
}

// ---------------------------------------------------------------------------
// Kernel B: Sbias[b,d] = sum_c (sum_j feat[b,j,c]) * kb3[c*16+d]
// 8 blocks x 256 threads, tree reduce over j.
// ---------------------------------------------------------------------------
__global__ __launch_bounds__(256) void sbias_kernel(const float* __restrict__ kb3)
{
    __shared__ float s_p[8][32];
    __shared__ float s_fs[32];
    int b = blockIdx.x;
    int tid = threadIdx.x;
    int c = tid & 31, grp = tid >> 5;
    float s = 0.f;
    for (int j = grp; j < PP; j += 8)
        s += g_feat[(b * PP + j) * 32 + c];
    s_p[grp][c] = s;
    __syncthreads();
    if (tid < 32) {
        float t = 0.f;
        #pragma unroll
        for (int g = 0; g < 8; g++) t += s_p[g][tid];
        s_fs[tid] = t;
    }
    __syncthreads();
    if (tid < 16) {
        float sb = 0.f;
        #pragma unroll
        for (int k = 0; k < 32; k++)
            sb = fmaf(s_fs[k], __ldg(kb3 + k * 16 + tid), sb);
        g_Sbias[b * 16 + tid] = sb;
    }
}

// ---------------------------------------------------------------------------
// Kernel C (hot): out[b,i,d] = relu( Sbias[b,d] + sum_{j,h} k2[i,j,h]*G[j,h,d] )
// Block = (b, 7-row i-tile); 224 blocks x 224 threads (7 warps), 2 blocks/SM.
// Contraction: warp w owns jj in {7w..7w+6}; lane = (g = h-half, d); thread
// holds G[jj, g*8..g*8+7, d] in 8 regs, reused across 7 i-accumulators.
// ---------------------------------------------------------------------------
__global__ __launch_bounds__(224, 2) void pair_kernel(
    const float* __restrict__ coords,
    const float* __restrict__ kW1, const float* __restrict__ kb1,
    const float* __restrict__ kW2, const float* __restrict__ kb2,
    float* __restrict__ out)
{
    extern __shared__ float sm[];
    float* s_k2  = sm;                           // IT*JT*K2P = 6860
    float* s_G   = s_k2 + IT * JT * K2P;         // JT*256    = 12544
    float* s_w   = s_G + JT * 256;               // 176
    float* s_ci  = s_w + 176;                    // 24
    float* s_cj  = s_ci + 24;                    // 148
    float* s_red = s_cj + 148;                   // 7*224 = 1568

    int tid = threadIdx.x;
    int b = blockIdx.x / NIT;
    int itile = blockIdx.x % NIT;
    int i0 = itile * IT;

    if (tid < 176) {
        float v;
        if (tid < 24)       v = kW1[tid];
        else if (tid < 32)  v = kb1[tid - 24];
        else if (tid < 160) v = kW2[tid - 32];
        else                v = kb2[tid - 160];
        s_w[tid] = v;
    }
    if (tid < IT * 3) s_ci[tid] = coords[(b * PP + i0) * 3 + tid];

    int w = tid >> 5, lane = tid & 31;
    int g = lane >> 4, d = lane & 15;

    float acc[IT];
    #pragma unroll
    for (int t = 0; t < IT; t++) acc[t] = 0.f;

    const float4* w2 = (const float4*)(s_w + 32);
    const float4* b2 = (const float4*)(s_w + 160);

    for (int tt = 0; tt < 4; tt++) {
        int j0 = tt * JT;
        __syncthreads();   // prior contraction done / initial loads done

        // stage G tile + j coords
        {
            const float4* src = (const float4*)(g_G + (b * PP + j0) * 256);
            float4* dst = (float4*)s_G;
            for (int q = tid; q < JT * 64; q += 224) dst[q] = src[q];
            if (tid < JT * 3) s_cj[tid] = coords[(b * PP + j0) * 3 + tid];
        }
        __syncthreads();   // s_cj (and s_G) staged before pair MLP reads them

        // pair MLP: 343 pairs over 224 threads
        for (int q = tid; q < IT * JT; q += 224) {
            int ii = q / JT;
            int jj = q - ii * JT;
            float r0 = s_cj[jj * 3 + 0] - s_ci[ii * 3 + 0];
            float r1 = s_cj[jj * 3 + 1] - s_ci[ii * 3 + 1];
            float r2 = s_cj[jj * 3 + 2] - s_ci[ii * 3 + 2];

            float a1[8];
            #pragma unroll
            for (int n = 0; n < 8; n++) {
                float a = s_w[24 + n];
                a = fmaf(r0, s_w[n], a);
                a = fmaf(r1, s_w[8 + n], a);
                a = fmaf(r2, s_w[16 + n], a);
                a1[n] = fmaxf(a, 0.f);
            }
            float a2[16];
            {
                float4 v0 = b2[0], v1 = b2[1], v2 = b2[2], v3 = b2[3];
                a2[0]=v0.x; a2[1]=v0.y; a2[2]=v0.z; a2[3]=v0.w;
                a2[4]=v1.x; a2[5]=v1.y; a2[6]=v1.z; a2[7]=v1.w;
                a2[8]=v2.x; a2[9]=v2.y; a2[10]=v2.z; a2[11]=v2.w;
                a2[12]=v3.x; a2[13]=v3.y; a2[14]=v3.z; a2[15]=v3.w;
            }
            #pragma unroll
            for (int k = 0; k < 8; k++) {
                float a = a1[k];
                #pragma unroll
                for (int n4 = 0; n4 < 4; n4++) {
                    float4 wv = w2[k * 4 + n4];
                    a2[n4*4+0] = fmaf(a, wv.x, a2[n4*4+0]);
                    a2[n4*4+1] = fmaf(a, wv.y, a2[n4*4+1]);
                    a2[n4*4+2] = fmaf(a, wv.z, a2[n4*4+2]);
                    a2[n4*4+3] = fmaf(a, wv.w, a2[n4*4+3]);
                }
            }
            float4* dst = (float4*)(s_k2 + q * K2P);
            #pragma unroll
            for (int n4 = 0; n4 < 4; n4++) {
                float4 v;
                v.x = fmaxf(a2[n4*4+0], 0.f);
                v.y = fmaxf(a2[n4*4+1], 0.f);
                v.z = fmaxf(a2[n4*4+2], 0.f);
                v.w = fmaxf(a2[n4*4+3], 0.f);
                dst[n4] = v;
            }
        }
        __syncthreads();

        // contraction
        #pragma unroll 1
        for (int m = 0; m < 7; m++) {
            int jj = w * 7 + m;
            const float* Gj = s_G + jj * 256 + g * 128 + d;
            float Gv[8];
            #pragma unroll
            for (int hh = 0; hh < 8; hh++) Gv[hh] = Gj[hh * 16];
            #pragma unroll
            for (int t = 0; t < IT; t++) {
                const float4* k4 = (const float4*)(s_k2 + (t * JT + jj) * K2P + g * 8);
                float4 ka = k4[0], kb = k4[1];
                float a = acc[t];
                a = fmaf(ka.x, Gv[0], a);
                a = fmaf(ka.y, Gv[1], a);
                a = fmaf(ka.z, Gv[2], a);
                a = fmaf(ka.w, Gv[3], a);
                a = fmaf(kb.x, Gv[4], a);
                a = fmaf(kb.y, Gv[5], a);
                a = fmaf(kb.z, Gv[6], a);
                a = fmaf(kb.w, Gv[7], a);
                acc[t] = a;
            }
        }
    }

    // cross-warp (+ h-half) reduction
    __syncthreads();
    #pragma unroll
    for (int t = 0; t < IT; t++)
        s_red[w * 224 + g * 112 + t * 16 + d] = acc[t];
    __syncthreads();
    if (tid < IT * 16) {
        int i = tid >> 4;
        int dd = tid & 15;
        float s = g_Sbias[b * 16 + dd];
        #pragma unroll
        for (int ww = 0; ww < 7; ww++) {
            s += s_red[ww * 224 + tid];
            s += s_red[ww * 224 + 112 + tid];
        }
        out[(b * PP + i0 + i) * 16 + dd] = fmaxf(s, 0.f);
    }
}

// ---------------------------------------------------------------------------
extern "C" void kernel_launch(void* const* d_in, const int* in_sizes, int n_in,
                              void* d_out, int out_size)
{
    const float* feature = (const float*)d_in[0];
    const float* pe      = (const float*)d_in[1];
    const float* coords  = (const float*)d_in[2];
    const float* dW1 = (const float*)d_in[3];
    const float* db1 = (const float*)d_in[4];
    const float* dW2 = (const float*)d_in[5];
    const float* db2 = (const float*)d_in[6];
    const float* dW3 = (const float*)d_in[7];
    const float* db3 = (const float*)d_in[8];
    const float* kW1 = (const float*)d_in[9];
    const float* kb1 = (const float*)d_in[10];
    const float* kW2 = (const float*)d_in[11];
    const float* kb2 = (const float*)d_in[12];
    const float* kW3 = (const float*)d_in[13];
    const float* kb3 = (const float*)d_in[14];
    float* out = (float*)d_out;

    const int smemFG = FG_TOT * (int)sizeof(float);
    const int smemB = (IT * JT * K2P + JT * 256 + 176 + 24 + 148 + 7 * 224)
                      * (int)sizeof(float);
    static bool attr_set = false;
    if (!attr_set) {
        cudaFuncSetAttribute(feat_G_kernel, cudaFuncAttributeMaxDynamicSharedMemorySize, smemFG);
        cudaFuncSetAttribute(pair_kernel, cudaFuncAttributeMaxDynamicSharedMemorySize, smemB);
        attr_set = true;
    }

    feat_G_kernel<<<196, 256, smemFG>>>(feature, pe, dW1, db1, dW2, db2, dW3, db3, kW3);
    sbias_kernel<<<BB, 256>>>(kb3);
    pair_kernel<<<BB * NIT, 224, smemB>>>(coords, kW1, kb1, kW2, kb2, out);
}